// round 8
// baseline (speedup 1.0000x reference)
#include <cuda_runtime.h>
#include <cstdint>

// Problem constants
#define B_  4
#define S_  2048
#define D_  768
#define H_  12
#define DK_ 64
#define M_  (B_ * S_)   // 8192

// Scratch: Q,K as tf32 bits [b,h,s,dk]; V as tf32 bits TRANSPOSED [b,h,dk,s];
// C fp32 concat [b,s,d].
__device__ uint32_t g_Q[(size_t)B_ * H_ * S_ * DK_];
__device__ uint32_t g_K[(size_t)B_ * H_ * S_ * DK_];
__device__ uint32_t g_V[(size_t)B_ * H_ * DK_ * S_];
__device__ float    g_C[(size_t)M_ * D_];

// ---------------------------------------------------------------------------
// Helpers
// ---------------------------------------------------------------------------
__device__ __forceinline__ uint32_t f2tf(float f) {
    uint32_t r;
    asm("cvt.rna.tf32.f32 %0, %1;" : "=r"(r) : "f"(f));
    return r;
}
__device__ __forceinline__ float ex2f(float x) {
    float r;
    asm("ex2.approx.f32 %0, %1;" : "=f"(r) : "f"(x));
    return r;
}
// D += A(16x8 row) * B(8x8 col), tf32 inputs, fp32 accumulate
__device__ __forceinline__ void mma8(float* c, const uint32_t* a, const uint32_t* b) {
    asm volatile(
        "mma.sync.aligned.m16n8k8.row.col.f32.tf32.tf32.f32 "
        "{%0,%1,%2,%3},{%4,%5,%6,%7},{%8,%9},{%0,%1,%2,%3};"
        : "+f"(c[0]), "+f"(c[1]), "+f"(c[2]), "+f"(c[3])
        : "r"(a[0]), "r"(a[1]), "r"(a[2]), "r"(a[3]), "r"(b[0]), "r"(b[1]));
}
__device__ __forceinline__ uint32_t smem_u32(const void* p) {
    uint32_t a;
    asm("{ .reg .u64 t; cvta.to.shared.u64 t, %1; cvt.u32.u64 %0, t; }" : "=r"(a) : "l"(p));
    return a;
}
__device__ __forceinline__ void cpasync16(uint32_t dst, const void* src) {
    asm volatile("cp.async.ca.shared.global [%0], [%1], 16;" :: "r"(dst), "l"(src));
}
#define CP_COMMIT() asm volatile("cp.async.commit_group;" ::: "memory")
#define CP_WAIT0()  asm volatile("cp.async.wait_group 0;" ::: "memory")

// ---------------------------------------------------------------------------
// GEMM core: acc = A[128 rows]@W[128 rows]^T over K=768, tf32 tensor cores.
// BM=128, BN=128, BK=32. 128 threads = 4 warps (2x2), warp tile 64x64.
// cp.async double-buffered smem (raw fp32); f2tf at fragment load.
// ---------------------------------------------------------------------------
#define G_STR 36
#define G_ARR (128 * G_STR)        // words per A or B tile
#define G_BUF (2 * G_ARR)          // A + B per buffer

// Mainloop shared by both GEMM kernels (Kdim = D_ = 768 fixed).
__device__ __forceinline__ void gemm_mainloop(
    const float* __restrict__ A, const float* __restrict__ W,
    float* smf, int m0, int n0, int tid, float acc[4][8][4])
{
    const uint32_t smem_base = smem_u32(smf);
    const int lane = tid & 31;
    const int wid  = tid >> 5;
    const int g    = lane >> 2;
    const int t4   = lane & 3;
    const int wm   = wid >> 1;
    const int wn   = wid & 1;
    const int ro = tid >> 3;          // 0..15
    const int ch = (tid & 7) * 4;     // 0..28 (floats)

    auto issue = [&](int buf, int k0) {
#pragma unroll
        for (int i = 0; i < 8; i++) {
            const int r = ro + i * 16;
            cpasync16(smem_base + (buf * G_BUF + r * G_STR + ch) * 4,
                      A + (size_t)(m0 + r) * D_ + k0 + ch);
            cpasync16(smem_base + (buf * G_BUF + G_ARR + r * G_STR + ch) * 4,
                      W + (size_t)(n0 + r) * D_ + k0 + ch);
        }
    };

    issue(0, 0);
    CP_COMMIT();

    const int nC = D_ / 32;   // 24
    for (int c = 0; c < nC; c++) {
        CP_WAIT0();
        __syncthreads();
        if (c + 1 < nC) {
            issue((c + 1) & 1, (c + 1) * 32);
            CP_COMMIT();
        }

        const float* As = smf + (c & 1) * G_BUF;
        const float* Bs = As + G_ARR;

#pragma unroll
        for (int kf = 0; kf < 4; kf++) {
            uint32_t a[4][4];
#pragma unroll
            for (int mf = 0; mf < 4; mf++) {
                const int r = wm * 64 + mf * 16 + g;
                a[mf][0] = f2tf(As[r * G_STR + kf * 8 + t4]);
                a[mf][1] = f2tf(As[(r + 8) * G_STR + kf * 8 + t4]);
                a[mf][2] = f2tf(As[r * G_STR + kf * 8 + t4 + 4]);
                a[mf][3] = f2tf(As[(r + 8) * G_STR + kf * 8 + t4 + 4]);
            }
#pragma unroll
            for (int nf = 0; nf < 8; nf++) {
                uint32_t b[2];
                const int r = wn * 64 + nf * 8 + g;
                b[0] = f2tf(Bs[r * G_STR + kf * 8 + t4]);
                b[1] = f2tf(Bs[r * G_STR + kf * 8 + t4 + 4]);
#pragma unroll
                for (int mf = 0; mf < 4; mf++)
                    mma8(acc[mf][nf], a[mf], b);
            }
        }
    }
}

// Fused Q/K/V projection GEMM: blockIdx.z selects input/weight/bias/output.
// z=0,1 (Q,K): tf32 bits [b,h,s,dk];  z=2 (V): tf32 bits [b,h,dk,s].
// One 1152-CTA launch -> 3.9 waves (vs 3 x 1.3-wave launches).
__global__ __launch_bounds__(128, 2) void gemm_proj_kernel(
    const float* __restrict__ qin, const float* __restrict__ kin,
    const float* __restrict__ vin,
    const float* __restrict__ Wq, const float* __restrict__ Wk,
    const float* __restrict__ Wv,
    const float* __restrict__ bq, const float* __restrict__ bk,
    const float* __restrict__ bv,
    uint32_t* __restrict__ oQ, uint32_t* __restrict__ oK,
    uint32_t* __restrict__ oV)
{
    extern __shared__ float smf[];
    const int z = blockIdx.z;
    const float* A    = (z == 0) ? qin : (z == 1) ? kin : vin;
    const float* W    = (z == 0) ? Wq  : (z == 1) ? Wk  : Wv;
    const float* bias = (z == 0) ? bq  : (z == 1) ? bk  : bv;
    uint32_t* Cout    = (z == 0) ? oQ  : (z == 1) ? oK  : oV;

    const int tid = threadIdx.x;
    const int lane = tid & 31;
    const int g  = lane >> 2;
    const int t4 = lane & 3;
    const int wm = (tid >> 5) >> 1;
    const int wn = (tid >> 5) & 1;
    const int m0 = blockIdx.x * 128;
    const int n0 = blockIdx.y * 128;

    float acc[4][8][4] = {};
    gemm_mainloop(A, W, smf, m0, n0, tid, acc);

#pragma unroll
    for (int mf = 0; mf < 4; mf++) {
#pragma unroll
        for (int nf = 0; nf < 8; nf++) {
            const int n = n0 + wn * 64 + nf * 8 + 2 * t4;
            const float b0 = bias[n];
            const float b1 = bias[n + 1];
#pragma unroll
            for (int rr = 0; rr < 2; rr++) {
                const int m = m0 + wm * 64 + mf * 16 + g + rr * 8;
                const float ox = acc[mf][nf][2 * rr + 0] + b0;
                const float oy = acc[mf][nf][2 * rr + 1] + b1;
                const int bidx = m >> 11;
                const int srow = m & (S_ - 1);
                const int h    = n >> 6;
                const int dk   = n & 63;
                if (z < 2) {
                    *(uint2*)(Cout + (((size_t)(bidx * H_ + h)) * S_ + srow) * DK_ + dk) =
                        make_uint2(f2tf(ox), f2tf(oy));
                } else {
                    const size_t base = ((size_t)(bidx * H_ + h)) * DK_;
                    Cout[(base + dk) * S_ + srow]     = f2tf(ox);
                    Cout[(base + dk + 1) * S_ + srow] = f2tf(oy);
                }
            }
        }
    }
}

// Output projection GEMM: fp32 row-major [M, N].
__global__ __launch_bounds__(128, 2) void gemm_out_kernel(
    const float* __restrict__ A, const float* __restrict__ W,
    const float* __restrict__ bias, float* __restrict__ Cout)
{
    extern __shared__ float smf[];
    const int tid = threadIdx.x;
    const int lane = tid & 31;
    const int g  = lane >> 2;
    const int t4 = lane & 3;
    const int wm = (tid >> 5) >> 1;
    const int wn = (tid >> 5) & 1;
    const int m0 = blockIdx.x * 128;
    const int n0 = blockIdx.y * 128;

    float acc[4][8][4] = {};
    gemm_mainloop(A, W, smf, m0, n0, tid, acc);

#pragma unroll
    for (int mf = 0; mf < 4; mf++) {
#pragma unroll
        for (int nf = 0; nf < 8; nf++) {
            const int n = n0 + wn * 64 + nf * 8 + 2 * t4;
            const float b0 = bias[n];
            const float b1 = bias[n + 1];
#pragma unroll
            for (int rr = 0; rr < 2; rr++) {
                const int m = m0 + wm * 64 + mf * 16 + g + rr * 8;
                *(float2*)(Cout + (size_t)m * D_ + n) =
                    make_float2(acc[mf][nf][2 * rr + 0] + b0,
                                acc[mf][nf][2 * rr + 1] + b1);
            }
        }
    }
}

// ---------------------------------------------------------------------------
// Fused flash attention (tf32 tensor cores).
// CTA: 128 queries x one (b,h). 4 warps x 32 query rows, 2 CTAs/SM —
// independent CTAs keep the tensor pipe fed while the other sits in its
// softmax/barrier chain.
// K/V pre-converted tf32 (V pre-transposed): double-buffered cp.async tiles.
// P never touches smem (S-fragment -> A-fragment shuffle permute).
// Scores in log2 domain (log2e folded into Q scale); ex2 softmax.
// Masked rows: scale 0 -> uniform softmax == reference (-1e9 rows).
// ---------------------------------------------------------------------------
#define TQ 128
#define TK 64
#define AT_STR 68
#define KV_WORDS (64 * AT_STR)             // one K or V tile
#define BUF_WORDS (2 * KV_WORDS)           // K + V per buffer

__global__ __launch_bounds__(128, 2) void attn_kernel(
    const int* __restrict__ mask, float* __restrict__ Cc)
{
    extern __shared__ uint32_t sm[];

    const int tid  = threadIdx.x;
    const int lane = tid & 31;
    const int wid  = tid >> 5;
    const int g    = lane >> 2;
    const int t4   = lane & 3;
    const int q0   = blockIdx.x * TQ;
    const int bh   = blockIdx.y;
    const int b    = bh / H_;
    const int h    = bh - b * H_;

    const uint32_t* Qg = g_Q + (size_t)bh * S_ * DK_;
    const uint32_t* Kg = g_K + (size_t)bh * S_ * DK_;
    const uint32_t* Vg = g_V + (size_t)bh * DK_ * S_;   // [dk][s]

    const uint32_t smem_base = smem_u32(sm);

    // copy mapping (K and V tiles): 128 threads, 2 rows each, 8 x 16B
    const int crow = tid >> 1;          // 0..63
    const int ccol = (tid & 1) * 32;    // word column base (0 or 32)

    // Warp-local rows
    int row[2][2];
    float sc[2][2];
#pragma unroll
    for (int mb = 0; mb < 2; mb++)
#pragma unroll
        for (int rr = 0; rr < 2; rr++) {
            row[mb][rr] = wid * 32 + mb * 16 + g + rr * 8;
            // 1/sqrt(64) * log2(e): scores land in log2 domain
            sc[mb][rr] = mask[b * S_ + q0 + row[mb][rr]] ? 0.18033688011112042f : 0.0f;
        }

    // Q fragments in registers (scale folded in, re-rounded to tf32)
    uint32_t qa[8][2][4];
#pragma unroll
    for (int kf = 0; kf < 8; kf++)
#pragma unroll
        for (int mb = 0; mb < 2; mb++) {
            qa[kf][mb][0] = f2tf(__uint_as_float(Qg[(size_t)(q0 + row[mb][0]) * DK_ + kf * 8 + t4]) * sc[mb][0]);
            qa[kf][mb][1] = f2tf(__uint_as_float(Qg[(size_t)(q0 + row[mb][1]) * DK_ + kf * 8 + t4]) * sc[mb][1]);
            qa[kf][mb][2] = f2tf(__uint_as_float(Qg[(size_t)(q0 + row[mb][0]) * DK_ + kf * 8 + t4 + 4]) * sc[mb][0]);
            qa[kf][mb][3] = f2tf(__uint_as_float(Qg[(size_t)(q0 + row[mb][1]) * DK_ + kf * 8 + t4 + 4]) * sc[mb][1]);
        }

    float mr[2][2], l[2][2];
    float oacc[2][8][4] = {};
#pragma unroll
    for (int mb = 0; mb < 2; mb++)
#pragma unroll
        for (int rr = 0; rr < 2; rr++) { mr[mb][rr] = -1e30f; l[mb][rr] = 0.0f; }

    auto issue_tile = [&](int buf, int k0) {
        const uint32_t kdst = smem_base + (buf * BUF_WORDS + crow * AT_STR + ccol) * 4;
        const uint32_t vdst = kdst + KV_WORDS * 4;
        const uint32_t* ksrc = Kg + (size_t)(k0 + crow) * DK_ + ccol;
        const uint32_t* vsrc = Vg + (size_t)crow * S_ + k0 + ccol;
#pragma unroll
        for (int i = 0; i < 8; i++) {
            cpasync16(kdst + i * 16, ksrc + i * 4);
            cpasync16(vdst + i * 16, vsrc + i * 4);
        }
    };

    issue_tile(0, 0);
    CP_COMMIT();

    const int nT = S_ / TK;
    for (int t = 0; t < nT; t++) {
        CP_WAIT0();
        __syncthreads();
        if (t + 1 < nT) {
            issue_tile((t + 1) & 1, (t + 1) * TK);
            CP_COMMIT();
        }

        const uint32_t* Ks = sm + (t & 1) * BUF_WORDS;
        const uint32_t* Vt = Ks + KV_WORDS;

        // S = Q @ K^T  (warp: 32 rows x 64 keys)
        float sacc[2][8][4] = {};
#pragma unroll
        for (int kf = 0; kf < 8; kf++) {
#pragma unroll
            for (int nf = 0; nf < 8; nf++) {
                uint32_t kb[2];
                const int r = nf * 8 + g;
                kb[0] = Ks[r * AT_STR + kf * 8 + t4];
                kb[1] = Ks[r * AT_STR + kf * 8 + t4 + 4];
                mma8(sacc[0][nf], qa[kf][0], kb);
                mma8(sacc[1][nf], qa[kf][1], kb);
            }
        }

        // Online softmax (log2 domain; quad reduce)
#pragma unroll
        for (int mb = 0; mb < 2; mb++) {
            float mx0 = -1e30f, mx1 = -1e30f;
#pragma unroll
            for (int nf = 0; nf < 8; nf++) {
                mx0 = fmaxf(mx0, fmaxf(sacc[mb][nf][0], sacc[mb][nf][1]));
                mx1 = fmaxf(mx1, fmaxf(sacc[mb][nf][2], sacc[mb][nf][3]));
            }
            mx0 = fmaxf(mx0, __shfl_xor_sync(0xffffffffu, mx0, 1));
            mx0 = fmaxf(mx0, __shfl_xor_sync(0xffffffffu, mx0, 2));
            mx1 = fmaxf(mx1, __shfl_xor_sync(0xffffffffu, mx1, 1));
            mx1 = fmaxf(mx1, __shfl_xor_sync(0xffffffffu, mx1, 2));

            const float mn0 = fmaxf(mr[mb][0], mx0);
            const float mn1 = fmaxf(mr[mb][1], mx1);
            const float c0 = ex2f(mr[mb][0] - mn0);
            const float c1 = ex2f(mr[mb][1] - mn1);
            mr[mb][0] = mn0; mr[mb][1] = mn1;

            float s0 = 0.0f, s1 = 0.0f;
#pragma unroll
            for (int nf = 0; nf < 8; nf++) {
                sacc[mb][nf][0] = ex2f(sacc[mb][nf][0] - mn0);
                sacc[mb][nf][1] = ex2f(sacc[mb][nf][1] - mn0);
                sacc[mb][nf][2] = ex2f(sacc[mb][nf][2] - mn1);
                sacc[mb][nf][3] = ex2f(sacc[mb][nf][3] - mn1);
                s0 += sacc[mb][nf][0] + sacc[mb][nf][1];
                s1 += sacc[mb][nf][2] + sacc[mb][nf][3];
            }
            s0 += __shfl_xor_sync(0xffffffffu, s0, 1);
            s0 += __shfl_xor_sync(0xffffffffu, s0, 2);
            s1 += __shfl_xor_sync(0xffffffffu, s1, 1);
            s1 += __shfl_xor_sync(0xffffffffu, s1, 2);
            l[mb][0] = l[mb][0] * c0 + s0;
            l[mb][1] = l[mb][1] * c1 + s1;

#pragma unroll
            for (int nf = 0; nf < 8; nf++) {
                oacc[mb][nf][0] *= c0; oacc[mb][nf][1] *= c0;
                oacc[mb][nf][2] *= c1; oacc[mb][nf][3] *= c1;
            }
        }

        // O += P @ V. P stays in registers: permute S-accumulator fragment
        // (cols 2t4,2t4+1) into A-operand fragment (cols t4,t4+4) via shfl.
        const int srcA = (lane & ~3) | (t4 >> 1);
        const int srcB = srcA + 2;
        const bool odd = (t4 & 1);
#pragma unroll
        for (int kf = 0; kf < 8; kf++) {
            uint32_t pa[2][4];
#pragma unroll
            for (int mb = 0; mb < 2; mb++) {
                const float c0 = sacc[mb][kf][0], c1 = sacc[mb][kf][1];
                const float c2 = sacc[mb][kf][2], c3 = sacc[mb][kf][3];
                const float u0A = __shfl_sync(0xffffffffu, c0, srcA);
                const float u1A = __shfl_sync(0xffffffffu, c1, srcA);
                const float u2A = __shfl_sync(0xffffffffu, c2, srcA);
                const float u3A = __shfl_sync(0xffffffffu, c3, srcA);
                const float u0B = __shfl_sync(0xffffffffu, c0, srcB);
                const float u1B = __shfl_sync(0xffffffffu, c1, srcB);
                const float u2B = __shfl_sync(0xffffffffu, c2, srcB);
                const float u3B = __shfl_sync(0xffffffffu, c3, srcB);
                pa[mb][0] = f2tf(odd ? u1A : u0A);
                pa[mb][1] = f2tf(odd ? u3A : u2A);
                pa[mb][2] = f2tf(odd ? u1B : u0B);
                pa[mb][3] = f2tf(odd ? u3B : u2B);
            }
#pragma unroll
            for (int nf = 0; nf < 8; nf++) {
                uint32_t vb[2];
                vb[0] = Vt[(nf * 8 + g) * AT_STR + kf * 8 + t4];
                vb[1] = Vt[(nf * 8 + g) * AT_STR + kf * 8 + t4 + 4];
                mma8(oacc[0][nf], pa[0], vb);
                mma8(oacc[1][nf], pa[1], vb);
            }
        }
    }

    // Epilogue: normalize, write concat [b, s, d] layout
#pragma unroll
    for (int mb = 0; mb < 2; mb++) {
        const float inv0 = 1.0f / l[mb][0];
        const float inv1 = 1.0f / l[mb][1];
        const size_t base0 = ((size_t)b * S_ + q0 + row[mb][0]) * D_ + h * DK_;
        const size_t base1 = ((size_t)b * S_ + q0 + row[mb][1]) * D_ + h * DK_;
#pragma unroll
        for (int nf = 0; nf < 8; nf++) {
            *(float2*)(Cc + base0 + nf * 8 + 2 * t4) =
                make_float2(oacc[mb][nf][0] * inv0, oacc[mb][nf][1] * inv0);
            *(float2*)(Cc + base1 + nf * 8 + 2 * t4) =
                make_float2(oacc[mb][nf][2] * inv1, oacc[mb][nf][3] * inv1);
        }
    }
}

// ---------------------------------------------------------------------------
extern "C" void kernel_launch(void* const* d_in, const int* in_sizes, int n_in,
                              void* d_out, int out_size)
{
    const float* q    = (const float*)d_in[0];
    const float* k    = (const float*)d_in[1];
    const float* v    = (const float*)d_in[2];
    const int*   mask = (const int*)  d_in[3];
    const float* Wq   = (const float*)d_in[4];
    const float* bq   = (const float*)d_in[5];
    const float* Wk   = (const float*)d_in[6];
    const float* bk   = (const float*)d_in[7];
    const float* Wv   = (const float*)d_in[8];
    const float* bv   = (const float*)d_in[9];
    const float* Wo   = (const float*)d_in[10];
    const float* bo   = (const float*)d_in[11];
    float* out = (float*)d_out;

    void *pQ, *pK, *pV, *pC;
    cudaGetSymbolAddress(&pQ, g_Q);
    cudaGetSymbolAddress(&pK, g_K);
    cudaGetSymbolAddress(&pV, g_V);
    cudaGetSymbolAddress(&pC, g_C);

    const dim3 blk(128);
    const int gemm_smem = 2 * G_BUF * (int)sizeof(float);  // 73728 B

    cudaFuncSetAttribute(gemm_proj_kernel, cudaFuncAttributeMaxDynamicSharedMemorySize, gemm_smem);
    cudaFuncSetAttribute(gemm_out_kernel,  cudaFuncAttributeMaxDynamicSharedMemorySize, gemm_smem);

    // Fused Q/K/V projections (one launch, 3.9 waves)
    gemm_proj_kernel<<<dim3(M_ / 128, D_ / 128, 3), blk, gemm_smem>>>(
        q, k, v, Wq, Wk, Wv, bq, bk, bv,
        (uint32_t*)pQ, (uint32_t*)pK, (uint32_t*)pV);

    // Fused attention -> concat layout (2 CTAs/SM)
    const int smem = 2 * BUF_WORDS * (int)sizeof(uint32_t);  // 69632 B
    cudaFuncSetAttribute(attn_kernel, cudaFuncAttributeMaxDynamicSharedMemorySize, smem);
    attn_kernel<<<dim3(S_ / TQ, B_ * H_), dim3(128), smem>>>(mask, (float*)pC);

    // Output projection
    gemm_out_kernel<<<dim3(M_ / 128, D_ / 128), blk, gemm_smem>>>(
        (const float*)pC, Wo, bo, out);
}

// round 10
// speedup vs baseline: 1.2230x; 1.2230x over previous
#include <cuda_runtime.h>
#include <cstdint>

// Problem constants
#define B_  4
#define S_  2048
#define D_  768
#define H_  12
#define DK_ 64
#define M_  (B_ * S_)   // 8192

// Scratch: Q,K as tf32 bits [b,h,s,dk]; V as tf32 bits TRANSPOSED [b,h,dk,s];
// C fp32 concat [b,s,d].
__device__ uint32_t g_Q[(size_t)B_ * H_ * S_ * DK_];
__device__ uint32_t g_K[(size_t)B_ * H_ * S_ * DK_];
__device__ uint32_t g_V[(size_t)B_ * H_ * DK_ * S_];
__device__ float    g_C[(size_t)M_ * D_];

// ---------------------------------------------------------------------------
// Helpers
// ---------------------------------------------------------------------------
__device__ __forceinline__ uint32_t f2tf(float f) {
    uint32_t r;
    asm("cvt.rna.tf32.f32 %0, %1;" : "=r"(r) : "f"(f));
    return r;
}
__device__ __forceinline__ float ex2f(float x) {
    float r;
    asm("ex2.approx.f32 %0, %1;" : "=f"(r) : "f"(x));
    return r;
}
// D += A(16x8 row) * B(8x8 col), tf32 inputs, fp32 accumulate
__device__ __forceinline__ void mma8(float* c, const uint32_t* a, const uint32_t* b) {
    asm volatile(
        "mma.sync.aligned.m16n8k8.row.col.f32.tf32.tf32.f32 "
        "{%0,%1,%2,%3},{%4,%5,%6,%7},{%8,%9},{%0,%1,%2,%3};"
        : "+f"(c[0]), "+f"(c[1]), "+f"(c[2]), "+f"(c[3])
        : "r"(a[0]), "r"(a[1]), "r"(a[2]), "r"(a[3]), "r"(b[0]), "r"(b[1]));
}
__device__ __forceinline__ uint32_t smem_u32(const void* p) {
    uint32_t a;
    asm("{ .reg .u64 t; cvta.to.shared.u64 t, %1; cvt.u32.u64 %0, t; }" : "=r"(a) : "l"(p));
    return a;
}
__device__ __forceinline__ void cpasync16(uint32_t dst, const void* src) {
    asm volatile("cp.async.ca.shared.global [%0], [%1], 16;" :: "r"(dst), "l"(src));
}
#define CP_COMMIT() asm volatile("cp.async.commit_group;" ::: "memory")
#define CP_WAIT0()  asm volatile("cp.async.wait_group 0;" ::: "memory")

// ---------------------------------------------------------------------------
// GEMM core: acc = A[128 rows]@W[128 rows]^T over K=768, tf32 tensor cores.
// BM=128, BN=128, BK=32. 128 threads = 4 warps (2x2), warp tile 64x64.
// cp.async double-buffered smem (raw fp32); f2tf at fragment load.
// ---------------------------------------------------------------------------
#define G_STR 36
#define G_ARR (128 * G_STR)        // words per A or B tile
#define G_BUF (2 * G_ARR)          // A + B per buffer

__device__ __forceinline__ void gemm_mainloop(
    const float* __restrict__ A, const float* __restrict__ W,
    float* smf, int m0, int n0, int tid, float acc[4][8][4])
{
    const uint32_t smem_base = smem_u32(smf);
    const int lane = tid & 31;
    const int wid  = tid >> 5;
    const int g    = lane >> 2;
    const int t4   = lane & 3;
    const int wm   = wid >> 1;
    const int wn   = wid & 1;
    const int ro = tid >> 3;          // 0..15
    const int ch = (tid & 7) * 4;     // 0..28 (floats)

    auto issue = [&](int buf, int k0) {
#pragma unroll
        for (int i = 0; i < 8; i++) {
            const int r = ro + i * 16;
            cpasync16(smem_base + (buf * G_BUF + r * G_STR + ch) * 4,
                      A + (size_t)(m0 + r) * D_ + k0 + ch);
            cpasync16(smem_base + (buf * G_BUF + G_ARR + r * G_STR + ch) * 4,
                      W + (size_t)(n0 + r) * D_ + k0 + ch);
        }
    };

    issue(0, 0);
    CP_COMMIT();

    const int nC = D_ / 32;   // 24
    for (int c = 0; c < nC; c++) {
        CP_WAIT0();
        __syncthreads();
        if (c + 1 < nC) {
            issue((c + 1) & 1, (c + 1) * 32);
            CP_COMMIT();
        }

        const float* As = smf + (c & 1) * G_BUF;
        const float* Bs = As + G_ARR;

#pragma unroll
        for (int kf = 0; kf < 4; kf++) {
            uint32_t a[4][4];
#pragma unroll
            for (int mf = 0; mf < 4; mf++) {
                const int r = wm * 64 + mf * 16 + g;
                a[mf][0] = f2tf(As[r * G_STR + kf * 8 + t4]);
                a[mf][1] = f2tf(As[(r + 8) * G_STR + kf * 8 + t4]);
                a[mf][2] = f2tf(As[r * G_STR + kf * 8 + t4 + 4]);
                a[mf][3] = f2tf(As[(r + 8) * G_STR + kf * 8 + t4 + 4]);
            }
#pragma unroll
            for (int nf = 0; nf < 8; nf++) {
                uint32_t b[2];
                const int r = wn * 64 + nf * 8 + g;
                b[0] = f2tf(Bs[r * G_STR + kf * 8 + t4]);
                b[1] = f2tf(Bs[r * G_STR + kf * 8 + t4 + 4]);
#pragma unroll
                for (int mf = 0; mf < 4; mf++)
                    mma8(acc[mf][nf], a[mf], b);
            }
        }
    }
}

// Fused Q/K/V projection GEMM: blockIdx.z selects input/weight/bias/output.
// z=0,1 (Q,K): tf32 bits [b,h,s,dk];  z=2 (V): tf32 bits [b,h,dk,s].
__global__ __launch_bounds__(128, 2) void gemm_proj_kernel(
    const float* __restrict__ qin, const float* __restrict__ kin,
    const float* __restrict__ vin,
    const float* __restrict__ Wq, const float* __restrict__ Wk,
    const float* __restrict__ Wv,
    const float* __restrict__ bq, const float* __restrict__ bk,
    const float* __restrict__ bv,
    uint32_t* __restrict__ oQ, uint32_t* __restrict__ oK,
    uint32_t* __restrict__ oV)
{
    extern __shared__ float smf[];
    const int z = blockIdx.z;
    const float* A    = (z == 0) ? qin : (z == 1) ? kin : vin;
    const float* W    = (z == 0) ? Wq  : (z == 1) ? Wk  : Wv;
    const float* bias = (z == 0) ? bq  : (z == 1) ? bk  : bv;
    uint32_t* Cout    = (z == 0) ? oQ  : (z == 1) ? oK  : oV;

    const int tid = threadIdx.x;
    const int lane = tid & 31;
    const int g  = lane >> 2;
    const int t4 = lane & 3;
    const int wm = (tid >> 5) >> 1;
    const int wn = (tid >> 5) & 1;
    const int m0 = blockIdx.x * 128;
    const int n0 = blockIdx.y * 128;

    float acc[4][8][4] = {};
    gemm_mainloop(A, W, smf, m0, n0, tid, acc);

#pragma unroll
    for (int mf = 0; mf < 4; mf++) {
#pragma unroll
        for (int nf = 0; nf < 8; nf++) {
            const int n = n0 + wn * 64 + nf * 8 + 2 * t4;
            const float b0 = bias[n];
            const float b1 = bias[n + 1];
#pragma unroll
            for (int rr = 0; rr < 2; rr++) {
                const int m = m0 + wm * 64 + mf * 16 + g + rr * 8;
                const float ox = acc[mf][nf][2 * rr + 0] + b0;
                const float oy = acc[mf][nf][2 * rr + 1] + b1;
                const int bidx = m >> 11;
                const int srow = m & (S_ - 1);
                const int h    = n >> 6;
                const int dk   = n & 63;
                if (z < 2) {
                    *(uint2*)(Cout + (((size_t)(bidx * H_ + h)) * S_ + srow) * DK_ + dk) =
                        make_uint2(f2tf(ox), f2tf(oy));
                } else {
                    const size_t base = ((size_t)(bidx * H_ + h)) * DK_;
                    Cout[(base + dk) * S_ + srow]     = f2tf(ox);
                    Cout[(base + dk + 1) * S_ + srow] = f2tf(oy);
                }
            }
        }
    }
}

// Output projection GEMM: fp32 row-major [M, N].
__global__ __launch_bounds__(128, 2) void gemm_out_kernel(
    const float* __restrict__ A, const float* __restrict__ W,
    const float* __restrict__ bias, float* __restrict__ Cout)
{
    extern __shared__ float smf[];
    const int tid = threadIdx.x;
    const int lane = tid & 31;
    const int g  = lane >> 2;
    const int t4 = lane & 3;
    const int wm = (tid >> 5) >> 1;
    const int wn = (tid >> 5) & 1;
    const int m0 = blockIdx.x * 128;
    const int n0 = blockIdx.y * 128;

    float acc[4][8][4] = {};
    gemm_mainloop(A, W, smf, m0, n0, tid, acc);

#pragma unroll
    for (int mf = 0; mf < 4; mf++) {
#pragma unroll
        for (int nf = 0; nf < 8; nf++) {
            const int n = n0 + wn * 64 + nf * 8 + 2 * t4;
            const float b0 = bias[n];
            const float b1 = bias[n + 1];
#pragma unroll
            for (int rr = 0; rr < 2; rr++) {
                const int m = m0 + wm * 64 + mf * 16 + g + rr * 8;
                *(float2*)(Cout + (size_t)m * D_ + n) =
                    make_float2(acc[mf][nf][2 * rr + 0] + b0,
                                acc[mf][nf][2 * rr + 1] + b1);
            }
        }
    }
}

// ---------------------------------------------------------------------------
// Fused flash attention (tf32 tensor cores) — R7 known-good config.
// CTA: 256 queries x one (b,h). 8 warps x 32 query rows.
// K/V pre-converted tf32 (V pre-transposed): double-buffered cp.async tiles.
// P never touches smem (S-fragment -> A-fragment shuffle permute).
// Scores in log2 domain (log2e folded into Q scale); ex2 softmax.
// Masked rows: scale 0 -> uniform softmax == reference (-1e9 rows).
// ---------------------------------------------------------------------------
#define TQ 256
#define TK 64
#define AT_STR 68
#define KV_WORDS (64 * AT_STR)             // one K or V tile
#define BUF_WORDS (2 * KV_WORDS)           // K + V per buffer

__global__ __launch_bounds__(256, 1) void attn_kernel(
    const int* __restrict__ mask, float* __restrict__ Cc)
{
    extern __shared__ uint32_t sm[];

    const int tid  = threadIdx.x;
    const int lane = tid & 31;
    const int wid  = tid >> 5;
    const int g    = lane >> 2;
    const int t4   = lane & 3;
    const int q0   = blockIdx.x * TQ;
    const int bh   = blockIdx.y;
    const int b    = bh / H_;
    const int h    = bh - b * H_;

    const uint32_t* Qg = g_Q + (size_t)bh * S_ * DK_;
    const uint32_t* Kg = g_K + (size_t)bh * S_ * DK_;
    const uint32_t* Vg = g_V + (size_t)bh * DK_ * S_;   // [dk][s]

    const uint32_t smem_base = smem_u32(sm);

    // copy mapping (K and V tiles): 4 x 16B per thread
    const int crow = tid >> 2;          // 0..63  (key row for K, d row for V)
    const int ccol = (tid & 3) * 16;    // word column base

    // Warp-local rows
    int row[2][2];
    float sc[2][2];
#pragma unroll
    for (int mb = 0; mb < 2; mb++)
#pragma unroll
        for (int rr = 0; rr < 2; rr++) {
            row[mb][rr] = wid * 32 + mb * 16 + g + rr * 8;
            // 1/sqrt(64) * log2(e): scores land in log2 domain
            sc[mb][rr] = mask[b * S_ + q0 + row[mb][rr]] ? 0.18033688011112042f : 0.0f;
        }

    // Q fragments in registers (scale folded in, re-rounded to tf32)
    uint32_t qa[8][2][4];
#pragma unroll
    for (int kf = 0; kf < 8; kf++)
#pragma unroll
        for (int mb = 0; mb < 2; mb++) {
            qa[kf][mb][0] = f2tf(__uint_as_float(Qg[(size_t)(q0 + row[mb][0]) * DK_ + kf * 8 + t4]) * sc[mb][0]);
            qa[kf][mb][1] = f2tf(__uint_as_float(Qg[(size_t)(q0 + row[mb][1]) * DK_ + kf * 8 + t4]) * sc[mb][1]);
            qa[kf][mb][2] = f2tf(__uint_as_float(Qg[(size_t)(q0 + row[mb][0]) * DK_ + kf * 8 + t4 + 4]) * sc[mb][0]);
            qa[kf][mb][3] = f2tf(__uint_as_float(Qg[(size_t)(q0 + row[mb][1]) * DK_ + kf * 8 + t4 + 4]) * sc[mb][1]);
        }

    float mr[2][2], l[2][2];
    float oacc[2][8][4] = {};
#pragma unroll
    for (int mb = 0; mb < 2; mb++)
#pragma unroll
        for (int rr = 0; rr < 2; rr++) { mr[mb][rr] = -1e30f; l[mb][rr] = 0.0f; }

    auto issue_tile = [&](int buf, int k0) {
        const uint32_t kdst = smem_base + (buf * BUF_WORDS + crow * AT_STR + ccol) * 4;
        const uint32_t vdst = kdst + KV_WORDS * 4;
        const uint32_t* ksrc = Kg + (size_t)(k0 + crow) * DK_ + ccol;
        const uint32_t* vsrc = Vg + (size_t)crow * S_ + k0 + ccol;
#pragma unroll
        for (int i = 0; i < 4; i++) {
            cpasync16(kdst + i * 16, ksrc + i * 4);
            cpasync16(vdst + i * 16, vsrc + i * 4);
        }
    };

    issue_tile(0, 0);
    CP_COMMIT();

    const int nT = S_ / TK;
    for (int t = 0; t < nT; t++) {
        CP_WAIT0();
        __syncthreads();
        if (t + 1 < nT) {
            issue_tile((t + 1) & 1, (t + 1) * TK);
            CP_COMMIT();
        }

        const uint32_t* Ks = sm + (t & 1) * BUF_WORDS;
        const uint32_t* Vt = Ks + KV_WORDS;

        // S = Q @ K^T  (warp: 32 rows x 64 keys)
        float sacc[2][8][4] = {};
#pragma unroll
        for (int kf = 0; kf < 8; kf++) {
#pragma unroll
            for (int nf = 0; nf < 8; nf++) {
                uint32_t kb[2];
                const int r = nf * 8 + g;
                kb[0] = Ks[r * AT_STR + kf * 8 + t4];
                kb[1] = Ks[r * AT_STR + kf * 8 + t4 + 4];
                mma8(sacc[0][nf], qa[kf][0], kb);
                mma8(sacc[1][nf], qa[kf][1], kb);
            }
        }

        // Online softmax (log2 domain; quad reduce)
#pragma unroll
        for (int mb = 0; mb < 2; mb++) {
            float mx0 = -1e30f, mx1 = -1e30f;
#pragma unroll
            for (int nf = 0; nf < 8; nf++) {
                mx0 = fmaxf(mx0, fmaxf(sacc[mb][nf][0], sacc[mb][nf][1]));
                mx1 = fmaxf(mx1, fmaxf(sacc[mb][nf][2], sacc[mb][nf][3]));
            }
            mx0 = fmaxf(mx0, __shfl_xor_sync(0xffffffffu, mx0, 1));
            mx0 = fmaxf(mx0, __shfl_xor_sync(0xffffffffu, mx0, 2));
            mx1 = fmaxf(mx1, __shfl_xor_sync(0xffffffffu, mx1, 1));
            mx1 = fmaxf(mx1, __shfl_xor_sync(0xffffffffu, mx1, 2));

            const float mn0 = fmaxf(mr[mb][0], mx0);
            const float mn1 = fmaxf(mr[mb][1], mx1);
            const float c0 = ex2f(mr[mb][0] - mn0);
            const float c1 = ex2f(mr[mb][1] - mn1);
            mr[mb][0] = mn0; mr[mb][1] = mn1;

            float s0 = 0.0f, s1 = 0.0f;
#pragma unroll
            for (int nf = 0; nf < 8; nf++) {
                sacc[mb][nf][0] = ex2f(sacc[mb][nf][0] - mn0);
                sacc[mb][nf][1] = ex2f(sacc[mb][nf][1] - mn0);
                sacc[mb][nf][2] = ex2f(sacc[mb][nf][2] - mn1);
                sacc[mb][nf][3] = ex2f(sacc[mb][nf][3] - mn1);
                s0 += sacc[mb][nf][0] + sacc[mb][nf][1];
                s1 += sacc[mb][nf][2] + sacc[mb][nf][3];
            }
            s0 += __shfl_xor_sync(0xffffffffu, s0, 1);
            s0 += __shfl_xor_sync(0xffffffffu, s0, 2);
            s1 += __shfl_xor_sync(0xffffffffu, s1, 1);
            s1 += __shfl_xor_sync(0xffffffffu, s1, 2);
            l[mb][0] = l[mb][0] * c0 + s0;
            l[mb][1] = l[mb][1] * c1 + s1;

#pragma unroll
            for (int nf = 0; nf < 8; nf++) {
                oacc[mb][nf][0] *= c0; oacc[mb][nf][1] *= c0;
                oacc[mb][nf][2] *= c1; oacc[mb][nf][3] *= c1;
            }
        }

        // O += P @ V. P stays in registers: permute S-accumulator fragment
        // (cols 2t4,2t4+1) into A-operand fragment (cols t4,t4+4) via shfl.
        const int srcA = (lane & ~3) | (t4 >> 1);
        const int srcB = srcA + 2;
        const bool odd = (t4 & 1);
#pragma unroll
        for (int kf = 0; kf < 8; kf++) {
            uint32_t pa[2][4];
#pragma unroll
            for (int mb = 0; mb < 2; mb++) {
                const float c0 = sacc[mb][kf][0], c1 = sacc[mb][kf][1];
                const float c2 = sacc[mb][kf][2], c3 = sacc[mb][kf][3];
                const float u0A = __shfl_sync(0xffffffffu, c0, srcA);
                const float u1A = __shfl_sync(0xffffffffu, c1, srcA);
                const float u2A = __shfl_sync(0xffffffffu, c2, srcA);
                const float u3A = __shfl_sync(0xffffffffu, c3, srcA);
                const float u0B = __shfl_sync(0xffffffffu, c0, srcB);
                const float u1B = __shfl_sync(0xffffffffu, c1, srcB);
                const float u2B = __shfl_sync(0xffffffffu, c2, srcB);
                const float u3B = __shfl_sync(0xffffffffu, c3, srcB);
                pa[mb][0] = f2tf(odd ? u1A : u0A);
                pa[mb][1] = f2tf(odd ? u3A : u2A);
                pa[mb][2] = f2tf(odd ? u1B : u0B);
                pa[mb][3] = f2tf(odd ? u3B : u2B);
            }
#pragma unroll
            for (int nf = 0; nf < 8; nf++) {
                uint32_t vb[2];
                vb[0] = Vt[(nf * 8 + g) * AT_STR + kf * 8 + t4];
                vb[1] = Vt[(nf * 8 + g) * AT_STR + kf * 8 + t4 + 4];
                mma8(oacc[0][nf], pa[0], vb);
                mma8(oacc[1][nf], pa[1], vb);
            }
        }
    }

    // Epilogue: normalize, write concat [b, s, d] layout
#pragma unroll
    for (int mb = 0; mb < 2; mb++) {
        const float inv0 = 1.0f / l[mb][0];
        const float inv1 = 1.0f / l[mb][1];
        const size_t base0 = ((size_t)b * S_ + q0 + row[mb][0]) * D_ + h * DK_;
        const size_t base1 = ((size_t)b * S_ + q0 + row[mb][1]) * D_ + h * DK_;
#pragma unroll
        for (int nf = 0; nf < 8; nf++) {
            *(float2*)(Cc + base0 + nf * 8 + 2 * t4) =
                make_float2(oacc[mb][nf][0] * inv0, oacc[mb][nf][1] * inv0);
            *(float2*)(Cc + base1 + nf * 8 + 2 * t4) =
                make_float2(oacc[mb][nf][2] * inv1, oacc[mb][nf][3] * inv1);
        }
    }
}

// ---------------------------------------------------------------------------
extern "C" void kernel_launch(void* const* d_in, const int* in_sizes, int n_in,
                              void* d_out, int out_size)
{
    const float* q    = (const float*)d_in[0];
    const float* k    = (const float*)d_in[1];
    const float* v    = (const float*)d_in[2];
    const int*   mask = (const int*)  d_in[3];
    const float* Wq   = (const float*)d_in[4];
    const float* bq   = (const float*)d_in[5];
    const float* Wk   = (const float*)d_in[6];
    const float* bk   = (const float*)d_in[7];
    const float* Wv   = (const float*)d_in[8];
    const float* bv   = (const float*)d_in[9];
    const float* Wo   = (const float*)d_in[10];
    const float* bo   = (const float*)d_in[11];
    float* out = (float*)d_out;

    void *pQ, *pK, *pV, *pC;
    cudaGetSymbolAddress(&pQ, g_Q);
    cudaGetSymbolAddress(&pK, g_K);
    cudaGetSymbolAddress(&pV, g_V);
    cudaGetSymbolAddress(&pC, g_C);

    const dim3 blk(128);
    const int gemm_smem = 2 * G_BUF * (int)sizeof(float);  // 73728 B

    cudaFuncSetAttribute(gemm_proj_kernel, cudaFuncAttributeMaxDynamicSharedMemorySize, gemm_smem);
    cudaFuncSetAttribute(gemm_out_kernel,  cudaFuncAttributeMaxDynamicSharedMemorySize, gemm_smem);

    // Fused Q/K/V projections (one launch)
    gemm_proj_kernel<<<dim3(M_ / 128, D_ / 128, 3), blk, gemm_smem>>>(
        q, k, v, Wq, Wk, Wv, bq, bk, bv,
        (uint32_t*)pQ, (uint32_t*)pK, (uint32_t*)pV);

    // Fused attention -> concat layout (R7 config: 256 thr, TQ=256)
    const int smem = 2 * BUF_WORDS * (int)sizeof(uint32_t);  // 69632 B
    cudaFuncSetAttribute(attn_kernel, cudaFuncAttributeMaxDynamicSharedMemorySize, smem);
    attn_kernel<<<dim3(S_ / TQ, B_ * H_), dim3(256), smem>>>(mask, (float*)pC);

    // Output projection
    gemm_out_kernel<<<dim3(M_ / 128, D_ / 128), blk, gemm_smem>>>(
        (const float*)pC, Wo, bo, out);
}